// round 4
// baseline (speedup 1.0000x reference)
#include <cuda_runtime.h>
#include <math.h>

// ---------------------------------------------------------------------------
// MS-SSIM on (32,3,512,512) fp32, 5 levels, in (s,d)=(x+y, x-y) basis.
// Only TWO packed f32x2 convolutions per pixel: conv(s,d) and conv(s^2,d^2).
//   mu1*mu2        = (mu_s^2 - mu_d^2)/4
//   mu1^2 + mu2^2  = (mu_s^2 + mu_d^2)/2
//   E12            = (Es2 - Ed2)/4,  E11+E22 = (Es2 + Ed2)/2
// Pyramid is stored packed (s,d) in one global float2 buffer.
// ---------------------------------------------------------------------------

#define NC 96
#define L1_PER 65536            // 256*256
#define L2_PER 16384            // 128*128
#define OFF_L1 0
#define OFF_L2 (NC * L1_PER)
#define SD_TOT (OFF_L2 + NC * L2_PER)

__device__ __align__(16) float2 g_sd[SD_TOT];
__device__ double g_acc_ssim[5];
__device__ double g_acc_cs[5];

#define GW0 0.12007838424321349f
#define GW1 0.23388075658535032f
#define GW2 0.29208171834287243f
#define C1V (0.01f * 0.01f)
#define C2V (0.03f * 0.03f)

typedef unsigned long long u64;

__device__ __forceinline__ u64 pk2(float lo, float hi) {
    u64 r; asm("mov.b64 %0, {%1, %2};" : "=l"(r) : "f"(lo), "f"(hi)); return r;
}
__device__ __forceinline__ void upk2(u64 v, float& lo, float& hi) {
    asm("mov.b64 {%0, %1}, %2;" : "=f"(lo), "=f"(hi) : "l"(v));
}
__device__ __forceinline__ u64 fma2_(u64 a, u64 b, u64 c) {
    u64 d; asm("fma.rn.f32x2 %0, %1, %2, %3;" : "=l"(d) : "l"(a), "l"(b), "l"(c)); return d;
}
__device__ __forceinline__ u64 mul2_(u64 a, u64 b) {
    u64 d; asm("mul.rn.f32x2 %0, %1, %2;" : "=l"(d) : "l"(a), "l"(b)); return d;
}
__device__ __forceinline__ u64 add2_(u64 a, u64 b) {
    u64 d; asm("add.rn.f32x2 %0, %1, %2;" : "=l"(d) : "l"(a), "l"(b)); return d;
}

__global__ void zero_acc_kernel() {
    int i = threadIdx.x;
    if (i < 5) { g_acc_ssim[i] = 0.0; g_acc_cs[i] = 0.0; }
}

// SSIM/CS from vertical-conv results: mu=(mu_s,mu_d), sq=(Es2,Ed2)
__device__ __forceinline__ void ssim_px(u64 mu, u64 sq, float& sa, float& ca)
{
    float ms2, md2; upk2(mul2_(mu, mu), ms2, md2);
    float es, ed;  upk2(sq, es, ed);
    float dm = ms2 - md2;          // 4*mu1mu2
    float sm = ms2 + md2;          // 2*(mu1^2+mu2^2)
    float lnum = fmaf(0.5f, dm, C1V);
    float lden = fmaf(0.5f, sm, C1V);
    float csn  = fmaf(0.5f, (es - ed) - dm, C2V);
    float csd  = fmaf(0.5f, (es + ed) - sm, C2V);
    float cs = __fdividef(csn, csd);
    sa = fmaf(__fdividef(lnum, lden), cs, sa);
    ca += cs;
}

// per-output horizontal taps (used by small kernel)
__device__ __forceinline__ void hmom(const float2* __restrict__ p,
                                     u64 w0p, u64 w1p, u64 w2p,
                                     u64& a_sd, u64& a_sq)
{
    a_sd = 0ull; a_sq = 0ull;
    #pragma unroll
    for (int k = 0; k < 5; k++) {
        u64 v = *reinterpret_cast<const u64*>(p + k);
        u64 wp = (k == 0 || k == 4) ? w0p : ((k == 1 || k == 3) ? w1p : w2p);
        a_sd = fma2_(wp, v, a_sd);
        a_sq = fma2_(wp, mul2_(v, v), a_sq);
    }
}

// ---------------------------------------------------------------------------
// Big-level kernel (levels 0 and 1): 32x32 tile, 256 threads
// ---------------------------------------------------------------------------
__global__ void __launch_bounds__(256)
ssim_big(const float* __restrict__ ext1, const float* __restrict__ ext2,
         int inOff, int outOff, int W, int H, int level)
{
    __shared__ __align__(16) float2 s[36][38];    // (s,d) halo tile, padded stride
    __shared__ __align__(16) float2 hA[36][34];   // (mu_s, mu_d) horizontal
    __shared__ __align__(16) float2 hB[36][34];   // (Es2, Ed2) horizontal
    __shared__ float red[2][8];

    const int tx = threadIdx.x, ty = threadIdx.y;
    const int tid = ty * 32 + tx;
    const int ox = blockIdx.x * 32, oy = blockIdx.y * 32;
    const int plane = blockIdx.z;

    const u64 w0p = pk2(GW0, GW0), w1p = pk2(GW1, GW1), w2p = pk2(GW2, GW2);

    const size_t planeOff = (size_t)plane * W * H;
    const float2* src = g_sd + inOff + planeOff;   // used when ext1 == null

    // ---- stage 1: load 36x36 halo as (s,d) ----
    bool interior = (ox >= 2) & (oy >= 2) & (ox + 34 <= W) & (oy + 34 <= H);
    if (interior) {
        #pragma unroll
        for (int it = 0; it < 3; it++) {
            int idx = tid + it * 256;
            if (idx < 648) {
                int r = idx / 18, pc = idx - 18 * r;
                size_t g = (size_t)(oy + r - 2) * W + (ox + 2 * pc - 2);
                if (ext1) {
                    float2 a = *reinterpret_cast<const float2*>(ext1 + planeOff + g);
                    float2 b = *reinterpret_cast<const float2*>(ext2 + planeOff + g);
                    *reinterpret_cast<float4*>(&s[r][2 * pc]) =
                        make_float4(a.x + b.x, a.x - b.x, a.y + b.y, a.y - b.y);
                } else {
                    *reinterpret_cast<float4*>(&s[r][2 * pc]) =
                        *reinterpret_cast<const float4*>(src + g);
                }
            }
        }
    } else {
        #pragma unroll
        for (int it = 0; it < 6; it++) {
            int idx = tid + it * 256;
            if (idx < 1296) {
                int r = idx / 36, c = idx - 36 * r;
                int gy = oy + r - 2, gx = ox + c - 2;
                float2 v = make_float2(0.f, 0.f);
                if ((gy >= 0) & (gy < H) & (gx >= 0) & (gx < W)) {
                    size_t g = (size_t)gy * W + gx;
                    if (ext1) {
                        float x = ext1[planeOff + g], y = ext2[planeOff + g];
                        v = make_float2(x + y, x - y);
                    } else {
                        v = src[g];
                    }
                }
                s[r][c] = v;
            }
        }
    }
    __syncthreads();

    // ---- stage 2: horizontal packed moments, 4 outputs per task ----
    for (int idx = tid; idx < 288; idx += 256) {
        int r = idx >> 3, c4 = (idx & 7) << 2;
        const float2* base = &s[r][c4];
        u64 v[8];
        #pragma unroll
        for (int t = 0; t < 4; t++) {
            ulonglong2 q = reinterpret_cast<const ulonglong2*>(base)[t];
            v[2 * t] = q.x; v[2 * t + 1] = q.y;
        }
        u64 vsq[8];
        #pragma unroll
        for (int i = 0; i < 8; i++) vsq[i] = mul2_(v[i], v[i]);

        u64 o_sd[4], o_sq[4];
        #pragma unroll
        for (int j = 0; j < 4; j++) {
            u64 a_sd = 0ull, a_sq = 0ull;
            #pragma unroll
            for (int k = 0; k < 5; k++) {
                u64 wp = (k == 0 || k == 4) ? w0p : ((k == 1 || k == 3) ? w1p : w2p);
                a_sd = fma2_(wp, v[j + k], a_sd);
                a_sq = fma2_(wp, vsq[j + k], a_sq);
            }
            o_sd[j] = a_sd; o_sq[j] = a_sq;
        }
        ulonglong2* pa = reinterpret_cast<ulonglong2*>(&hA[r][c4]);
        ulonglong2* pb = reinterpret_cast<ulonglong2*>(&hB[r][c4]);
        pa[0] = make_ulonglong2(o_sd[0], o_sd[1]);
        pa[1] = make_ulonglong2(o_sd[2], o_sd[3]);
        pb[0] = make_ulonglong2(o_sq[0], o_sq[1]);
        pb[1] = make_ulonglong2(o_sq[2], o_sq[3]);
    }
    __syncthreads();

    // ---- fused 2x2 avg-pool -> next level (linear in (s,d)) ----
    {
        int pr = tid >> 4, pc = tid & 15;
        int r0 = 2 + 2 * pr, c0 = 2 + 2 * pc;
        u64 a = *reinterpret_cast<const u64*>(&s[r0][c0]);
        u64 b = *reinterpret_cast<const u64*>(&s[r0][c0 + 1]);
        u64 c = *reinterpret_cast<const u64*>(&s[r0 + 1][c0]);
        u64 d = *reinterpret_cast<const u64*>(&s[r0 + 1][c0 + 1]);
        u64 q = mul2_(pk2(0.25f, 0.25f), add2_(add2_(a, b), add2_(c, d)));
        int Wh = W >> 1, Hh = H >> 1;
        size_t o = (size_t)outOff + (size_t)plane * Wh * Hh
                 + (size_t)(oy / 2 + pr) * Wh + (ox / 2 + pc);
        *reinterpret_cast<u64*>(&g_sd[o]) = q;
    }

    // ---- stage 3: vertical pass, register ring, 4 rows/thread ----
    const int b = ty * 4;
    u64 qm[5], qs[5];
    #pragma unroll
    for (int j = 0; j < 5; j++) {
        qm[j] = *reinterpret_cast<const u64*>(&hA[b + j][tx]);
        qs[j] = *reinterpret_cast<const u64*>(&hB[b + j][tx]);
    }

    float sacc = 0.f, cacc = 0.f;
    #pragma unroll
    for (int i = 0; i < 4; i++) {
        if (i > 0) {
            int sl = (i + 4) % 5;
            qm[sl] = *reinterpret_cast<const u64*>(&hA[b + i + 4][tx]);
            qs[sl] = *reinterpret_cast<const u64*>(&hB[b + i + 4][tx]);
        }
        u64 mu = 0ull, sq = 0ull;
        #pragma unroll
        for (int k = 0; k < 5; k++) {
            int sl = (i + k) % 5;
            u64 wp = (k == 0 || k == 4) ? w0p : ((k == 1 || k == 3) ? w1p : w2p);
            mu = fma2_(wp, qm[sl], mu);
            sq = fma2_(wp, qs[sl], sq);
        }
        ssim_px(mu, sq, sacc, cacc);
    }

    // ---- reduction ----
    #pragma unroll
    for (int off = 16; off; off >>= 1) {
        sacc += __shfl_down_sync(0xffffffffu, sacc, off);
        cacc += __shfl_down_sync(0xffffffffu, cacc, off);
    }
    if (tx == 0) { red[0][ty] = sacc; red[1][ty] = cacc; }
    __syncthreads();
    if (tid == 0) {
        float ss = 0.f, cc = 0.f;
        #pragma unroll
        for (int i = 0; i < 8; i++) { ss += red[0][i]; cc += red[1][i]; }
        atomicAdd(&g_acc_ssim[level], (double)ss);
        atomicAdd(&g_acc_cs[level], (double)cc);
    }
}

// ---------------------------------------------------------------------------
// Fused small-level kernel: levels 2,3,4 — one block per plane, 1024 threads.
//   A: 132x132 (padded 128), B: 68x68 (padded 64), C: 36x36 (padded 32)
// ---------------------------------------------------------------------------
#define SM_FLOAT2 (17424 + 4624 + 1296)
#define SM_BYTES (SM_FLOAT2 * 8)
#define SMALL_T 1024
#define SMALL_W 32

template<int S>
__device__ __forceinline__ void ssim_plane(const float2* __restrict__ P, int stride,
                                           int tx, int ty, float& sa, float& ca)
{
    constexpr int RPT = S / SMALL_W;
    const u64 w0p = pk2(GW0, GW0), w1p = pk2(GW1, GW1), w2p = pk2(GW2, GW2);

    #pragma unroll
    for (int ct = 0; ct < S / 32; ct++) {
        int c = tx + 32 * ct;
        int r0 = ty * RPT;
        u64 m_sd[5], m_sq[5];

        #pragma unroll
        for (int j = 0; j < 5; j++)
            hmom(P + (r0 + j) * stride + c, w0p, w1p, w2p, m_sd[j], m_sq[j]);

        #pragma unroll
        for (int i = 0; i < RPT; i++) {
            if (i > 0) {
                int sl = (i + 4) % 5;
                hmom(P + (r0 + i + 4) * stride + c, w0p, w1p, w2p, m_sd[sl], m_sq[sl]);
            }
            u64 mu = 0ull, sq = 0ull;
            #pragma unroll
            for (int k = 0; k < 5; k++) {
                int sl = (i + k) % 5;
                u64 wp = (k == 0 || k == 4) ? w0p : ((k == 1 || k == 3) ? w1p : w2p);
                mu = fma2_(wp, m_sd[sl], mu);
                sq = fma2_(wp, m_sq[sl], sq);
            }
            ssim_px(mu, sq, sa, ca);
        }
    }
}

__global__ void __launch_bounds__(SMALL_T)
ssim_small()
{
    extern __shared__ float2 sm[];
    float2* A = sm;
    float2* B = sm + 17424;
    float2* C = sm + 17424 + 4624;
    __shared__ float red[6][SMALL_W];

    const int tx = threadIdx.x, ty = threadIdx.y;
    const int tid = ty * 32 + tx;
    const int plane = blockIdx.x;

    const float2* src = g_sd + OFF_L2 + (size_t)plane * L2_PER;

    // zero B and C borders (zero everything, cheap)
    for (int idx = tid; idx < 4624 + 1296; idx += SMALL_T) {
        if (idx < 4624) B[idx] = make_float2(0.f, 0.f);
        else            C[idx - 4624] = make_float2(0.f, 0.f);
    }
    // load A (132x132 padded)
    for (int idx = tid; idx < 17424; idx += SMALL_T) {
        int r = idx / 132, c = idx - 132 * r;
        int gr = r - 2, gc = c - 2;
        float2 v = make_float2(0.f, 0.f);
        if ((gr >= 0) & (gr < 128) & (gc >= 0) & (gc < 128))
            v = src[gr * 128 + gc];
        A[idx] = v;
    }
    __syncthreads();

    float s2 = 0.f, c2 = 0.f, s3 = 0.f, c3 = 0.f, s4 = 0.f, c4 = 0.f;

    ssim_plane<128>(A, 132, tx, ty, s2, c2);
    for (int idx = tid; idx < 4096; idx += SMALL_T) {
        int i = idx >> 6, j = idx & 63;
        int base = (2 * i + 2) * 132 + (2 * j + 2);
        u64 a = *reinterpret_cast<const u64*>(&A[base]);
        u64 b = *reinterpret_cast<const u64*>(&A[base + 1]);
        u64 c = *reinterpret_cast<const u64*>(&A[base + 132]);
        u64 d = *reinterpret_cast<const u64*>(&A[base + 133]);
        *reinterpret_cast<u64*>(&B[(i + 2) * 68 + j + 2]) =
            mul2_(pk2(0.25f, 0.25f), add2_(add2_(a, b), add2_(c, d)));
    }
    __syncthreads();

    ssim_plane<64>(B, 68, tx, ty, s3, c3);
    for (int idx = tid; idx < 1024; idx += SMALL_T) {
        int i = idx >> 5, j = idx & 31;
        int base = (2 * i + 2) * 68 + (2 * j + 2);
        u64 a = *reinterpret_cast<const u64*>(&B[base]);
        u64 b = *reinterpret_cast<const u64*>(&B[base + 1]);
        u64 c = *reinterpret_cast<const u64*>(&B[base + 68]);
        u64 d = *reinterpret_cast<const u64*>(&B[base + 69]);
        *reinterpret_cast<u64*>(&C[(i + 2) * 36 + j + 2]) =
            mul2_(pk2(0.25f, 0.25f), add2_(add2_(a, b), add2_(c, d)));
    }
    __syncthreads();

    ssim_plane<32>(C, 36, tx, ty, s4, c4);

    float vals[6] = {s2, c2, s3, c3, s4, c4};
    #pragma unroll
    for (int v = 0; v < 6; v++) {
        float x = vals[v];
        #pragma unroll
        for (int off = 16; off; off >>= 1)
            x += __shfl_down_sync(0xffffffffu, x, off);
        if (tx == 0) red[v][ty] = x;
    }
    __syncthreads();
    if (tid == 0) {
        float t[6] = {0.f, 0.f, 0.f, 0.f, 0.f, 0.f};
        #pragma unroll
        for (int i = 0; i < SMALL_W; i++)
            #pragma unroll
            for (int v = 0; v < 6; v++) t[v] += red[v][i];
        atomicAdd(&g_acc_ssim[2], (double)t[0]);
        atomicAdd(&g_acc_cs[2],   (double)t[1]);
        atomicAdd(&g_acc_ssim[3], (double)t[2]);
        atomicAdd(&g_acc_cs[3],   (double)t[3]);
        atomicAdd(&g_acc_ssim[4], (double)t[4]);
        atomicAdd(&g_acc_cs[4],   (double)t[5]);
    }
}

__global__ void finalize_kernel(float* __restrict__ out)
{
    const double w[5] = {(double)0.0448f, (double)0.2856f, (double)0.3001f,
                         (double)0.2363f, (double)0.1333f};
    double cnt4 = (double)NC * 32.0 * 32.0;
    double s4 = g_acc_ssim[4] / cnt4;
    double ss4 = (s4 + 1.0) * 0.5;
    double p2 = pow(ss4, w[4]);

    double res = 1.0;
    #pragma unroll
    for (int i = 0; i < 4; i++) {
        int dim = 512 >> i;
        double cnt = (double)NC * (double)dim * (double)dim;
        double cs = g_acc_cs[i] / cnt;
        double m = (cs + 1.0) * 0.5;
        res *= pow(m, w[i]) * p2;
    }
    out[0] = (float)res;
}

extern "C" void kernel_launch(void* const* d_in, const int* in_sizes, int n_in,
                              void* d_out, int out_size)
{
    const float* img1 = (const float*)d_in[0];
    const float* img2 = (const float*)d_in[1];
    float* out = (float*)d_out;

    cudaFuncSetAttribute(ssim_small,
                         cudaFuncAttributeMaxDynamicSharedMemorySize, SM_BYTES);

    zero_acc_kernel<<<1, 32>>>();

    dim3 blk(32, 8);
    ssim_big<<<dim3(16, 16, NC), blk>>>(img1, img2, 0, OFF_L1, 512, 512, 0);
    ssim_big<<<dim3(8, 8, NC), blk>>>(nullptr, nullptr, OFF_L1, OFF_L2, 256, 256, 1);
    ssim_small<<<NC, dim3(32, SMALL_W), SM_BYTES>>>();
    finalize_kernel<<<1, 1>>>(out);
}

// round 5
// speedup vs baseline: 1.0279x; 1.0279x over previous
#include <cuda_runtime.h>
#include <math.h>

// ---------------------------------------------------------------------------
// MS-SSIM on (32,3,512,512) fp32, 5 levels, in (s,d)=(x+y, x-y) basis.
// Two packed f32x2 convolutions per pixel: conv(s,d), conv(s^2,d^2).
// L0, L1: 32x64 tiles, 256 threads, dynamic smem, fused 2x2 pool.
// L2+L3+L4: one block per plane, 512 threads, whole pyramid in smem.
// ---------------------------------------------------------------------------

#define NC 96
#define L1_PER 65536            // 256*256
#define L2_PER 16384            // 128*128
#define OFF_L1 0
#define OFF_L2 (NC * L1_PER)
#define SD_TOT (OFF_L2 + NC * L2_PER)

__device__ __align__(16) float2 g_sd[SD_TOT];
__device__ double g_acc_ssim[5];
__device__ double g_acc_cs[5];

#define GW0 0.12007838424321349f
#define GW1 0.23388075658535032f
#define GW2 0.29208171834287243f
#define C1V (0.01f * 0.01f)
#define C2V (0.03f * 0.03f)

typedef unsigned long long u64;

__device__ __forceinline__ u64 pk2(float lo, float hi) {
    u64 r; asm("mov.b64 %0, {%1, %2};" : "=l"(r) : "f"(lo), "f"(hi)); return r;
}
__device__ __forceinline__ void upk2(u64 v, float& lo, float& hi) {
    asm("mov.b64 {%0, %1}, %2;" : "=f"(lo), "=f"(hi) : "l"(v));
}
__device__ __forceinline__ u64 fma2_(u64 a, u64 b, u64 c) {
    u64 d; asm("fma.rn.f32x2 %0, %1, %2, %3;" : "=l"(d) : "l"(a), "l"(b), "l"(c)); return d;
}
__device__ __forceinline__ u64 mul2_(u64 a, u64 b) {
    u64 d; asm("mul.rn.f32x2 %0, %1, %2;" : "=l"(d) : "l"(a), "l"(b)); return d;
}
__device__ __forceinline__ u64 add2_(u64 a, u64 b) {
    u64 d; asm("add.rn.f32x2 %0, %1, %2;" : "=l"(d) : "l"(a), "l"(b)); return d;
}

__global__ void zero_acc_kernel() {
    int i = threadIdx.x;
    if (i < 5) { g_acc_ssim[i] = 0.0; g_acc_cs[i] = 0.0; }
}

// SSIM/CS from vertical-conv results: mu=(mu_s,mu_d), sq=(Es2,Ed2)
__device__ __forceinline__ void ssim_px(u64 mu, u64 sq, float& sa, float& ca)
{
    float ms2, md2; upk2(mul2_(mu, mu), ms2, md2);
    float es, ed;  upk2(sq, es, ed);
    float dm = ms2 - md2;          // 4*mu1mu2
    float sm = ms2 + md2;          // 2*(mu1^2+mu2^2)
    float lnum = fmaf(0.5f, dm, C1V);
    float lden = fmaf(0.5f, sm, C1V);
    float csn  = fmaf(0.5f, (es - ed) - dm, C2V);
    float csd  = fmaf(0.5f, (es + ed) - sm, C2V);
    float cs = __fdividef(csn, csd);
    sa = fmaf(__fdividef(lnum, lden), cs, sa);
    ca += cs;
}

// horizontal 5-tap packed moments
__device__ __forceinline__ void hmom(const float2* __restrict__ p,
                                     u64 w0p, u64 w1p, u64 w2p,
                                     u64& a_sd, u64& a_sq)
{
    a_sd = 0ull; a_sq = 0ull;
    #pragma unroll
    for (int k = 0; k < 5; k++) {
        u64 v = *reinterpret_cast<const u64*>(p + k);
        u64 wp = (k == 0 || k == 4) ? w0p : ((k == 1 || k == 3) ? w1p : w2p);
        a_sd = fma2_(wp, v, a_sd);
        a_sq = fma2_(wp, mul2_(v, v), a_sq);
    }
}

// ---------------------------------------------------------------------------
// Big-level kernel (levels 0, 1): 32-wide x 64-tall tile, 256 threads.
// Dynamic smem: s[68][38], hA[68][32], hB[68][32]  (float2)
// ---------------------------------------------------------------------------
#define BIG_SM_F2 (68 * 38 + 2 * 68 * 32)
#define BIG_SM_BYTES (BIG_SM_F2 * 8)

__global__ void __launch_bounds__(256)
ssim_big(const float* __restrict__ ext1, const float* __restrict__ ext2,
         int inOff, int outOff, int W, int H, int level)
{
    extern __shared__ __align__(16) float2 dsm[];
    float2* s  = dsm;                  // [68][38]
    float2* hA = dsm + 68 * 38;        // [68][32] (mu_s, mu_d)
    float2* hB = hA + 68 * 32;         // [68][32] (Es2, Ed2)
    __shared__ float red[2][8];

    const int tx = threadIdx.x, ty = threadIdx.y;
    const int tid = ty * 32 + tx;
    const int ox = blockIdx.x * 32, oy = blockIdx.y * 64;
    const int plane = blockIdx.z;

    const u64 w0p = pk2(GW0, GW0), w1p = pk2(GW1, GW1), w2p = pk2(GW2, GW2);

    const size_t planeOff = (size_t)plane * W * H;
    const float2* src = g_sd + inOff + planeOff;   // used when ext1 == null

    // ---- stage 1: load 68x36 halo as (s,d) into s (stride 38) ----
    bool interior = (ox >= 2) & (oy >= 2) & (ox + 34 <= W) & (oy + 66 <= H);
    if (interior) {
        // 68 rows x 18 float4 (36 float2 cols)
        #pragma unroll
        for (int it = 0; it < 5; it++) {
            int idx = tid + it * 256;
            if (idx < 1224) {
                int r = idx / 18, pc = idx - 18 * r;
                size_t g = (size_t)(oy + r - 2) * W + (ox + 2 * pc - 2);
                if (ext1) {
                    float2 a = *reinterpret_cast<const float2*>(ext1 + planeOff + g);
                    float2 b = *reinterpret_cast<const float2*>(ext2 + planeOff + g);
                    *reinterpret_cast<float4*>(&s[r * 38 + 2 * pc]) =
                        make_float4(a.x + b.x, a.x - b.x, a.y + b.y, a.y - b.y);
                } else {
                    *reinterpret_cast<float4*>(&s[r * 38 + 2 * pc]) =
                        *reinterpret_cast<const float4*>(src + g);
                }
            }
        }
    } else {
        #pragma unroll
        for (int it = 0; it < 10; it++) {
            int idx = tid + it * 256;
            if (idx < 2448) {
                int r = idx / 36, c = idx - 36 * r;
                int gy = oy + r - 2, gx = ox + c - 2;
                float2 v = make_float2(0.f, 0.f);
                if ((gy >= 0) & (gy < H) & (gx >= 0) & (gx < W)) {
                    size_t g = (size_t)gy * W + gx;
                    if (ext1) {
                        float x = ext1[planeOff + g], y = ext2[planeOff + g];
                        v = make_float2(x + y, x - y);
                    } else {
                        v = src[g];
                    }
                }
                s[r * 38 + c] = v;
            }
        }
    }
    __syncthreads();

    // ---- stage 2: horizontal packed moments, one column per thread ----
    for (int r = ty; r < 68; r += 8) {
        u64 a_sd, a_sq;
        hmom(&s[r * 38 + tx], w0p, w1p, w2p, a_sd, a_sq);
        *reinterpret_cast<u64*>(&hA[r * 32 + tx]) = a_sd;
        *reinterpret_cast<u64*>(&hB[r * 32 + tx]) = a_sq;
    }
    __syncthreads();

    // ---- fused 2x2 avg-pool -> next level (linear in (s,d)) ----
    {
        int Wh = W >> 1, Hh = H >> 1;
        #pragma unroll
        for (int it = 0; it < 2; it++) {
            int idx = tid + it * 256;
            int pr = idx >> 4, pc = idx & 15;
            int r0 = 2 + 2 * pr, c0 = 2 + 2 * pc;
            u64 a = *reinterpret_cast<const u64*>(&s[r0 * 38 + c0]);
            u64 b = *reinterpret_cast<const u64*>(&s[r0 * 38 + c0 + 1]);
            u64 c = *reinterpret_cast<const u64*>(&s[(r0 + 1) * 38 + c0]);
            u64 d = *reinterpret_cast<const u64*>(&s[(r0 + 1) * 38 + c0 + 1]);
            u64 q = mul2_(pk2(0.25f, 0.25f), add2_(add2_(a, b), add2_(c, d)));
            size_t o = (size_t)outOff + (size_t)plane * Wh * Hh
                     + (size_t)(oy / 2 + pr) * Wh + (ox / 2 + pc);
            *reinterpret_cast<u64*>(&g_sd[o]) = q;
        }
    }

    // ---- stage 3: vertical pass, register ring, 8 rows/thread ----
    const int b = ty * 8;
    u64 qm[5], qs[5];
    #pragma unroll
    for (int j = 0; j < 5; j++) {
        qm[j] = *reinterpret_cast<const u64*>(&hA[(b + j) * 32 + tx]);
        qs[j] = *reinterpret_cast<const u64*>(&hB[(b + j) * 32 + tx]);
    }

    float sacc = 0.f, cacc = 0.f;
    #pragma unroll
    for (int i = 0; i < 8; i++) {
        if (i > 0) {
            int sl = (i + 4) % 5;
            qm[sl] = *reinterpret_cast<const u64*>(&hA[(b + i + 4) * 32 + tx]);
            qs[sl] = *reinterpret_cast<const u64*>(&hB[(b + i + 4) * 32 + tx]);
        }
        u64 mu = 0ull, sq = 0ull;
        #pragma unroll
        for (int k = 0; k < 5; k++) {
            int sl = (i + k) % 5;
            u64 wp = (k == 0 || k == 4) ? w0p : ((k == 1 || k == 3) ? w1p : w2p);
            mu = fma2_(wp, qm[sl], mu);
            sq = fma2_(wp, qs[sl], sq);
        }
        ssim_px(mu, sq, sacc, cacc);
    }

    // ---- reduction ----
    #pragma unroll
    for (int off = 16; off; off >>= 1) {
        sacc += __shfl_down_sync(0xffffffffu, sacc, off);
        cacc += __shfl_down_sync(0xffffffffu, cacc, off);
    }
    if (tx == 0) { red[0][ty] = sacc; red[1][ty] = cacc; }
    __syncthreads();
    if (tid == 0) {
        float ss = 0.f, cc = 0.f;
        #pragma unroll
        for (int i = 0; i < 8; i++) { ss += red[0][i]; cc += red[1][i]; }
        atomicAdd(&g_acc_ssim[level], (double)ss);
        atomicAdd(&g_acc_cs[level], (double)cc);
    }
}

// ---------------------------------------------------------------------------
// Fused small-level kernel: levels 2,3,4 — one block per plane, 512 threads.
//   A: 132x132 (padded 128), B: 68x68 (padded 64), C: 36x36 (padded 32)
// ---------------------------------------------------------------------------
#define SM_FLOAT2 (17424 + 4624 + 1296)
#define SM_BYTES (SM_FLOAT2 * 8)
#define SMALL_T 512
#define SMALL_W 16

template<int S>
__device__ __forceinline__ void ssim_plane(const float2* __restrict__ P, int stride,
                                           int tx, int ty, float& sa, float& ca)
{
    constexpr int RPT = S / SMALL_W;
    const u64 w0p = pk2(GW0, GW0), w1p = pk2(GW1, GW1), w2p = pk2(GW2, GW2);

    #pragma unroll
    for (int ct = 0; ct < S / 32; ct++) {
        int c = tx + 32 * ct;
        int r0 = ty * RPT;
        u64 m_sd[5], m_sq[5];

        #pragma unroll
        for (int j = 0; j < 5; j++)
            hmom(P + (r0 + j) * stride + c, w0p, w1p, w2p, m_sd[j], m_sq[j]);

        #pragma unroll
        for (int i = 0; i < RPT; i++) {
            if (i > 0) {
                int sl = (i + 4) % 5;
                hmom(P + (r0 + i + 4) * stride + c, w0p, w1p, w2p, m_sd[sl], m_sq[sl]);
            }
            u64 mu = 0ull, sq = 0ull;
            #pragma unroll
            for (int k = 0; k < 5; k++) {
                int sl = (i + k) % 5;
                u64 wp = (k == 0 || k == 4) ? w0p : ((k == 1 || k == 3) ? w1p : w2p);
                mu = fma2_(wp, m_sd[sl], mu);
                sq = fma2_(wp, m_sq[sl], sq);
            }
            ssim_px(mu, sq, sa, ca);
        }
    }
}

__global__ void __launch_bounds__(SMALL_T)
ssim_small()
{
    extern __shared__ __align__(16) float2 sm[];
    float2* A = sm;
    float2* B = sm + 17424;
    float2* C = sm + 17424 + 4624;
    __shared__ float red[6][SMALL_W];

    const int tx = threadIdx.x, ty = threadIdx.y;
    const int tid = ty * 32 + tx;
    const int plane = blockIdx.x;

    const float2* src = g_sd + OFF_L2 + (size_t)plane * L2_PER;

    // zero B, C fully and A borders
    for (int idx = tid; idx < 4624 + 1296; idx += SMALL_T) {
        if (idx < 4624) B[idx] = make_float2(0.f, 0.f);
        else            C[idx - 4624] = make_float2(0.f, 0.f);
    }
    for (int idx = tid; idx < 1040; idx += SMALL_T) {
        int o;
        if (idx < 528) {
            int rr = idx / 132, c = idx - 132 * rr;
            int rows4[4] = {0, 1, 130, 131};
            o = rows4[rr] * 132 + c;
        } else {
            int k = idx - 528;
            int r = 2 + (k >> 2);
            int cols4[4] = {0, 1, 130, 131};
            o = r * 132 + cols4[k & 3];
        }
        A[o] = make_float2(0.f, 0.f);
    }
    // load A interior: 128 rows x 64 float4
    for (int idx = tid; idx < 8192; idx += SMALL_T) {
        int r = idx >> 6, c4 = idx & 63;
        *reinterpret_cast<float4*>(&A[(r + 2) * 132 + 2 + 2 * c4]) =
            *reinterpret_cast<const float4*>(src + r * 128 + 2 * c4);
    }
    __syncthreads();

    float s2 = 0.f, c2 = 0.f, s3 = 0.f, c3 = 0.f, s4 = 0.f, c4v = 0.f;

    ssim_plane<128>(A, 132, tx, ty, s2, c2);
    for (int idx = tid; idx < 4096; idx += SMALL_T) {
        int i = idx >> 6, j = idx & 63;
        int base = (2 * i + 2) * 132 + (2 * j + 2);
        u64 a = *reinterpret_cast<const u64*>(&A[base]);
        u64 b = *reinterpret_cast<const u64*>(&A[base + 1]);
        u64 c = *reinterpret_cast<const u64*>(&A[base + 132]);
        u64 d = *reinterpret_cast<const u64*>(&A[base + 133]);
        *reinterpret_cast<u64*>(&B[(i + 2) * 68 + j + 2]) =
            mul2_(pk2(0.25f, 0.25f), add2_(add2_(a, b), add2_(c, d)));
    }
    __syncthreads();

    ssim_plane<64>(B, 68, tx, ty, s3, c3);
    for (int idx = tid; idx < 1024; idx += SMALL_T) {
        int i = idx >> 5, j = idx & 31;
        int base = (2 * i + 2) * 68 + (2 * j + 2);
        u64 a = *reinterpret_cast<const u64*>(&B[base]);
        u64 b = *reinterpret_cast<const u64*>(&B[base + 1]);
        u64 c = *reinterpret_cast<const u64*>(&B[base + 68]);
        u64 d = *reinterpret_cast<const u64*>(&B[base + 69]);
        *reinterpret_cast<u64*>(&C[(i + 2) * 36 + j + 2]) =
            mul2_(pk2(0.25f, 0.25f), add2_(add2_(a, b), add2_(c, d)));
    }
    __syncthreads();

    ssim_plane<32>(C, 36, tx, ty, s4, c4v);

    float vals[6] = {s2, c2, s3, c3, s4, c4v};
    #pragma unroll
    for (int v = 0; v < 6; v++) {
        float x = vals[v];
        #pragma unroll
        for (int off = 16; off; off >>= 1)
            x += __shfl_down_sync(0xffffffffu, x, off);
        if (tx == 0) red[v][ty] = x;
    }
    __syncthreads();
    if (tid == 0) {
        float t[6] = {0.f, 0.f, 0.f, 0.f, 0.f, 0.f};
        #pragma unroll
        for (int i = 0; i < SMALL_W; i++)
            #pragma unroll
            for (int v = 0; v < 6; v++) t[v] += red[v][i];
        atomicAdd(&g_acc_ssim[2], (double)t[0]);
        atomicAdd(&g_acc_cs[2],   (double)t[1]);
        atomicAdd(&g_acc_ssim[3], (double)t[2]);
        atomicAdd(&g_acc_cs[3],   (double)t[3]);
        atomicAdd(&g_acc_ssim[4], (double)t[4]);
        atomicAdd(&g_acc_cs[4],   (double)t[5]);
    }
}

__global__ void finalize_kernel(float* __restrict__ out)
{
    const double w[5] = {(double)0.0448f, (double)0.2856f, (double)0.3001f,
                         (double)0.2363f, (double)0.1333f};
    double cnt4 = (double)NC * 32.0 * 32.0;
    double s4 = g_acc_ssim[4] / cnt4;
    double ss4 = (s4 + 1.0) * 0.5;
    double p2 = pow(ss4, w[4]);

    double res = 1.0;
    #pragma unroll
    for (int i = 0; i < 4; i++) {
        int dim = 512 >> i;
        double cnt = (double)NC * (double)dim * (double)dim;
        double cs = g_acc_cs[i] / cnt;
        double m = (cs + 1.0) * 0.5;
        res *= pow(m, w[i]) * p2;
    }
    out[0] = (float)res;
}

extern "C" void kernel_launch(void* const* d_in, const int* in_sizes, int n_in,
                              void* d_out, int out_size)
{
    const float* img1 = (const float*)d_in[0];
    const float* img2 = (const float*)d_in[1];
    float* out = (float*)d_out;

    cudaFuncSetAttribute(ssim_big,
                         cudaFuncAttributeMaxDynamicSharedMemorySize, BIG_SM_BYTES);
    cudaFuncSetAttribute(ssim_small,
                         cudaFuncAttributeMaxDynamicSharedMemorySize, SM_BYTES);

    zero_acc_kernel<<<1, 32>>>();

    dim3 blk(32, 8);
    ssim_big<<<dim3(16, 8, NC), blk, BIG_SM_BYTES>>>(img1, img2, 0, OFF_L1, 512, 512, 0);
    ssim_big<<<dim3(8, 4, NC), blk, BIG_SM_BYTES>>>(nullptr, nullptr, OFF_L1, OFF_L2, 256, 256, 1);
    ssim_small<<<NC, dim3(32, SMALL_W), SM_BYTES>>>();
    finalize_kernel<<<1, 1>>>(out);
}